// round 9
// baseline (speedup 1.0000x reference)
#include <cuda_runtime.h>
#include <cuda_bf16.h>

// RHS of 2-field Burgers-like PDE on nonuniform 2048x4096 grid.
// Inputs (metadata order): t[1], state[2*NX*NY], x[NX], y[NY], mu[1]
// Output: [2, NX, NY] float32.
//
// R9: R6 structure (front-batched 6-row float4 window, best measured MLP)
// with all stencil math rewritten as packed f32x2 (FFMA2) instructions.
// d1 coefficients are stored NEGATED so the advection terms are pure FMAs.

#define NX_MAX 2048
#define NY_MAX 4096
#define FULLMASK 0xffffffffu

typedef unsigned long long ull;

// x-direction coefficients: AoS (warp-uniform broadcast loads)
__device__ float4 g_cxA[NX_MAX];   // (-d1a, -d1b, -d1c, d2a)
__device__ float2 g_cxB[NX_MAX];   // (d2b, d2c)
// y-direction coefficients: SoA, 16B-aligned for float4 loads (d1 negated)
__device__ __align__(16) float g_cy1a[NY_MAX];
__device__ __align__(16) float g_cy1b[NY_MAX];
__device__ __align__(16) float g_cy1c[NY_MAX];
__device__ __align__(16) float g_cy2a[NY_MAX];
__device__ __align__(16) float g_cy2b[NY_MAX];
__device__ __align__(16) float g_cy2c[NY_MAX];

__device__ __forceinline__ void stencil_coeffs(const float* __restrict__ g,
                                               int n, int k, float* c) {
    if (k == 0) {
        float hA = g[1] - g[0], hB = g[2] - g[1];
        c[0] = -(2.f * hA + hB) / (hA * (hA + hB));
        c[1] = (hA + hB) / (hA * hB);
        c[2] = -hA / (hB * (hA + hB));
        c[3] = 2.f / (hA * (hA + hB));
        c[4] = -2.f / (hA * hB);
        c[5] = 2.f / (hB * (hA + hB));
    } else if (k == n - 1) {
        float hC = g[n - 2] - g[n - 3], hD = g[n - 1] - g[n - 2];
        c[0] = hD / (hC * (hC + hD));
        c[1] = -(hC + hD) / (hC * hD);
        c[2] = (hC + 2.f * hD) / (hD * (hC + hD));
        c[3] = 2.f / (hC * (hC + hD));
        c[4] = -2.f / (hC * hD);
        c[5] = 2.f / (hD * (hC + hD));
    } else {
        float h1 = g[k] - g[k - 1], h2 = g[k + 1] - g[k];
        c[0] = -h2 / (h1 * (h1 + h2));
        c[1] = (h2 - h1) / (h1 * h2);
        c[2] = h1 / (h2 * (h1 + h2));
        c[3] = 2.f / (h1 * (h1 + h2));
        c[4] = -2.f / (h1 * h2);
        c[5] = 2.f / (h2 * (h1 + h2));
    }
    // Negate d1 coefficients: advection terms become pure FMAs.
    c[0] = -c[0]; c[1] = -c[1]; c[2] = -c[2];
}

__global__ __launch_bounds__(256)
void coeff_kernel(const float* __restrict__ x, int nx,
                  const float* __restrict__ y, int ny) {
    int k = blockIdx.x * blockDim.x + threadIdx.x;
    float c[6];
    if (k < nx) {
        stencil_coeffs(x, nx, k, c);
        g_cxA[k] = make_float4(c[0], c[1], c[2], c[3]);
        g_cxB[k] = make_float2(c[4], c[5]);
    }
    if (k < ny) {
        stencil_coeffs(y, ny, k, c);
        g_cy1a[k] = c[0]; g_cy1b[k] = c[1]; g_cy1c[k] = c[2];
        g_cy2a[k] = c[3]; g_cy2b[k] = c[4]; g_cy2c[k] = c[5];
    }
}

__device__ __forceinline__ float4 ld4(const float* p) {
    return *reinterpret_cast<const float4*>(p);
}
__device__ __forceinline__ void st4(float* p, float4 v) {
    *reinterpret_cast<float4*>(p) = v;
}

// ---- packed f32x2 helpers ----
__device__ __forceinline__ ull pk(float lo, float hi) {
    ull d;
    asm("mov.b64 %0, {%1, %2};" : "=l"(d)
        : "r"(__float_as_uint(lo)), "r"(__float_as_uint(hi)));
    return d;
}
__device__ __forceinline__ void upk(ull p, float& lo, float& hi) {
    unsigned a, b;
    asm("mov.b64 {%0, %1}, %2;" : "=r"(a), "=r"(b) : "l"(p));
    lo = __uint_as_float(a); hi = __uint_as_float(b);
}
__device__ __forceinline__ ull mul2(ull a, ull b) {
    ull d; asm("mul.rn.f32x2 %0, %1, %2;" : "=l"(d) : "l"(a), "l"(b)); return d;
}
__device__ __forceinline__ ull add2(ull a, ull b) {
    ull d; asm("add.rn.f32x2 %0, %1, %2;" : "=l"(d) : "l"(a), "l"(b)); return d;
}
__device__ __forceinline__ ull fma2(ull a, ull b, ull c) {
    ull d; asm("fma.rn.f32x2 %0, %1, %2, %3;" : "=l"(d) : "l"(a), "l"(b), "l"(c));
    return d;
}
// 3-point stencil: p0*k0 + p1*k1 + p2*k2
__device__ __forceinline__ ull tri2(ull p0, ull p1, ull p2, ull k0, ull k1, ull k2) {
    return fma2(p2, k2, fma2(p1, k1, mul2(p0, k0)));
}

// Warp owns 128 aligned columns; lane owns 4 (float4 = two f32x2 pairs).
// Each thread computes 4 consecutive i-rows from a front-batched 6-row window.
__global__ __launch_bounds__(256)
void rhs_kernel(const float* __restrict__ state,
                const float* __restrict__ mu_p,
                float* __restrict__ out, int nx, int ny) {
    const int lane = threadIdx.x;
    const int base = blockIdx.x * 128;
    const int j0 = base + lane * 4;
    if (j0 >= ny) return;
    const int i0 = (blockIdx.y * blockDim.y + threadIdx.y) * 4;
    const unsigned plane = (unsigned)nx * (unsigned)ny;
    const float* __restrict__ u = state;
    const float* __restrict__ v = state + plane;
    const float mu = mu_p[0];
    const ull mu2 = pk(mu, mu);
    const ull K2 = pk(0.01f, 0.01f);

    // 6-row window (rows i0-1 .. i0+4, i-clamped), packed as f32x2 pairs.
    ull u01[6], u23[6], v01[6], v23[6];
#pragma unroll
    for (int k = 0; k < 6; k++) {
        int ir = min(max(i0 - 1 + k, 0), nx - 1);
        unsigned off = (unsigned)ir * (unsigned)ny + (unsigned)j0;
        float4 a = ld4(u + off);
        float4 b = ld4(v + off);
        u01[k] = pk(a.x, a.y); u23[k] = pk(a.z, a.w);
        v01[k] = pk(b.x, b.y); v23[k] = pk(b.z, b.w);
    }

    // Halo columns (warp-edge neighbors), compute rows only.
    float hu[4] = {0, 0, 0, 0}, hv[4] = {0, 0, 0, 0};
    const bool is_halo = (lane == 0) || (lane == 31);
    if (is_halo) {
        int jh = (lane == 0) ? max(base - 1, 0) : min(base + 128, ny - 1);
#pragma unroll
        for (int r = 0; r < 4; r++) {
            unsigned off = (unsigned)(i0 + r) * (unsigned)ny + (unsigned)jh;
            hu[r] = __ldg(u + off);
            hv[r] = __ldg(v + off);
        }
    }

    // y-coefficient pairs for this lane's 4 columns (d1 negated in memory)
    const float4 c1a = ld4(&g_cy1a[j0]);
    const float4 c1b = ld4(&g_cy1b[j0]);
    const float4 c1c = ld4(&g_cy1c[j0]);
    const float4 c2a = ld4(&g_cy2a[j0]);
    const float4 c2b = ld4(&g_cy2b[j0]);
    const float4 c2c = ld4(&g_cy2c[j0]);
    const ull y1a01 = pk(c1a.x, c1a.y), y1a23 = pk(c1a.z, c1a.w);
    const ull y1b01 = pk(c1b.x, c1b.y), y1b23 = pk(c1b.z, c1b.w);
    const ull y1c01 = pk(c1c.x, c1c.y), y1c23 = pk(c1c.z, c1c.w);
    const ull y2a01 = pk(c2a.x, c2a.y), y2a23 = pk(c2a.z, c2a.w);
    const ull y2b01 = pk(c2b.x, c2b.y), y2b23 = pk(c2b.z, c2b.w);
    const ull y2c01 = pk(c2c.x, c2c.y), y2c23 = pk(c2c.z, c2c.w);

    const bool e0b = (j0 == 0);            // column .x is the global left edge
    const bool e3b = (j0 + 3 == ny - 1);   // column .w is the global right edge
    const unsigned obase = (unsigned)i0 * (unsigned)ny + (unsigned)j0;

#pragma unroll
    for (int r = 0; r < 4; r++) {
        const int i = i0 + r;
        const ull U01 = u01[r + 1], U23 = u23[r + 1];
        const ull V01 = v01[r + 1], V23 = v23[r + 1];
        float Ux, Uy, Uz, Uw, Vx, Vy, Vz, Vw;
        upk(U01, Ux, Uy); upk(U23, Uz, Uw);
        upk(V01, Vx, Vy); upk(V23, Vz, Vw);

        // Warp-edge neighbors via shuffle; lanes 0/31 patch from halo loads.
        float lu = __shfl_up_sync(FULLMASK, Uw, 1);
        float ru = __shfl_down_sync(FULLMASK, Ux, 1);
        float lv = __shfl_up_sync(FULLMASK, Vw, 1);
        float rv = __shfl_down_sync(FULLMASK, Vx, 1);
        if (lane == 0)  { lu = hu[r]; lv = hv[r]; }
        if (lane == 31) { ru = hu[r]; rv = hv[r]; }

        // Per-element y-stencil triples. At j==0 the one-sided stencil reads
        // columns {0,1,2} = (x,y,z); at j==ny-1 it reads (y,z,w).
        float a0u = e0b ? Ux : lu,  b0u = e0b ? Uy : Ux, g0u = e0b ? Uz : Uy;
        float a0v = e0b ? Vx : lv,  b0v = e0b ? Vy : Vx, g0v = e0b ? Vz : Vy;
        float a3u = e3b ? Uy : Uz,  b3u = e3b ? Uz : Uw, g3u = e3b ? Uw : ru;
        float a3v = e3b ? Vy : Vz,  b3v = e3b ? Vz : Vw, g3v = e3b ? Vw : rv;

        // Shifted operand pairs for the y-stencils
        const ull Pau = pk(a0u, Ux), Pbu = pk(b0u, Uy), Pcu = pk(g0u, Uz);
        const ull Qau = pk(Uy, a3u), Qbu = pk(Uz, b3u), Qcu = pk(Uw, g3u);
        const ull Pav = pk(a0v, Vx), Pbv = pk(b0v, Vy), Pcv = pk(g0v, Vz);
        const ull Qav = pk(Vy, a3v), Qbv = pk(Vz, b3v), Qcv = pk(Vw, g3v);

        // y-derivatives (nd1y = -d1y thanks to negated coefficients)
        const ull nd1y_u01 = tri2(Pau, Pbu, Pcu, y1a01, y1b01, y1c01);
        const ull d2y_u01  = tri2(Pau, Pbu, Pcu, y2a01, y2b01, y2c01);
        const ull nd1y_u23 = tri2(Qau, Qbu, Qcu, y1a23, y1b23, y1c23);
        const ull d2y_u23  = tri2(Qau, Qbu, Qcu, y2a23, y2b23, y2c23);
        const ull nd1y_v01 = tri2(Pav, Pbv, Pcv, y1a01, y1b01, y1c01);
        const ull d2y_v01  = tri2(Pav, Pbv, Pcv, y2a01, y2b01, y2c01);
        const ull nd1y_v23 = tri2(Qav, Qbv, Qcv, y1a23, y1b23, y1c23);
        const ull d2y_v23  = tri2(Qav, Qbv, Qcv, y2a23, y2b23, y2c23);

        // x-stencil triples from the window (one-sided at i==nx-1; i==0 row
        // is fully zeroed by the reference so the default triple is fine).
        const bool last = (i == nx - 1);
        const int rm = (r > 0) ? r - 1 : 0;   // safe: last implies r==3 here
        const ull X0_01 = last ? u01[rm] : u01[r];
        const ull X1_01 = last ? u01[r]  : u01[r + 1];
        const ull X2_01 = last ? u01[r + 1] : u01[r + 2];
        const ull X0_23 = last ? u23[rm] : u23[r];
        const ull X1_23 = last ? u23[r]  : u23[r + 1];
        const ull X2_23 = last ? u23[r + 1] : u23[r + 2];
        const ull Y0_01 = last ? v01[rm] : v01[r];
        const ull Y1_01 = last ? v01[r]  : v01[r + 1];
        const ull Y2_01 = last ? v01[r + 1] : v01[r + 2];
        const ull Y0_23 = last ? v23[rm] : v23[r];
        const ull Y1_23 = last ? v23[r]  : v23[r + 1];
        const ull Y2_23 = last ? v23[r + 1] : v23[r + 2];

        // x-coefficients (warp-uniform), replicated into both f32x2 lanes
        const float4 cxa = g_cxA[i];
        const float2 cxb = g_cxB[i];
        const ull x1a = pk(cxa.x, cxa.x), x1b = pk(cxa.y, cxa.y), x1c = pk(cxa.z, cxa.z);
        const ull x2a = pk(cxa.w, cxa.w), x2b = pk(cxb.x, cxb.x), x2c = pk(cxb.y, cxb.y);

        const ull nd1x_u01 = tri2(X0_01, X1_01, X2_01, x1a, x1b, x1c);
        const ull d2x_u01  = tri2(X0_01, X1_01, X2_01, x2a, x2b, x2c);
        const ull nd1x_u23 = tri2(X0_23, X1_23, X2_23, x1a, x1b, x1c);
        const ull d2x_u23  = tri2(X0_23, X1_23, X2_23, x2a, x2b, x2c);
        const ull nd1x_v01 = tri2(Y0_01, Y1_01, Y2_01, x1a, x1b, x1c);
        const ull d2x_v01  = tri2(Y0_01, Y1_01, Y2_01, x2a, x2b, x2c);
        const ull nd1x_v23 = tri2(Y0_23, Y1_23, Y2_23, x1a, x1b, x1c);
        const ull d2x_v23  = tri2(Y0_23, Y1_23, Y2_23, x2a, x2b, x2c);

        // du = mu*(d2y+d2x) + u*(-d1x) + v*(-d1y) + 0.01 ; dv analogous (no +0.01)
        const ull du01 = fma2(mu2, add2(d2y_u01, d2x_u01),
                         fma2(U01, nd1x_u01, fma2(V01, nd1y_u01, K2)));
        const ull du23 = fma2(mu2, add2(d2y_u23, d2x_u23),
                         fma2(U23, nd1x_u23, fma2(V23, nd1y_u23, K2)));
        const ull dv01 = fma2(mu2, add2(d2y_v01, d2x_v01),
                         fma2(U01, nd1x_v01, mul2(V01, nd1y_v01)));
        const ull dv23 = fma2(mu2, add2(d2y_v23, d2x_v23),
                         fma2(U23, nd1x_v23, mul2(V23, nd1y_v23)));

        float4 du, dv;
        upk(du01, du.x, du.y); upk(du23, du.z, du.w);
        upk(dv01, dv.x, dv.y); upk(dv23, dv.z, dv.w);

        // Boundary zeroing per reference (entire i==0 row zeroed for both)
        if (i == 0) { du = make_float4(0.f, 0.f, 0.f, 0.f);
                      dv = make_float4(0.f, 0.f, 0.f, 0.f); }
        if (e0b) { du.x = 0.f; dv.x = 0.f; }
        if (e3b) { du.w = 0.f; }

        unsigned o = obase + (unsigned)r * (unsigned)ny;
        st4(out + o, du);
        st4(out + plane + o, dv);
    }
}

extern "C" void kernel_launch(void* const* d_in, const int* in_sizes, int n_in,
                              void* d_out, int out_size) {
    const float* state = (const float*)d_in[1];
    const float* x = (const float*)d_in[2];
    const float* y = (const float*)d_in[3];
    const float* mu = (const float*)d_in[4];
    int nx = in_sizes[2];
    int ny = in_sizes[3];
    float* out = (float*)d_out;

    int nmax = nx > ny ? nx : ny;
    coeff_kernel<<<(nmax + 255) / 256, 256>>>(x, nx, y, ny);

    dim3 block(32, 8);                        // warp = 128 columns, 32 i-rows/block
    dim3 grid((ny + 127) / 128, (nx + 31) / 32);
    rhs_kernel<<<grid, block>>>(state, mu, out, nx, ny);
}

// round 10
// speedup vs baseline: 1.3512x; 1.3512x over previous
#include <cuda_runtime.h>
#include <cuda_bf16.h>

// RHS of 2-field Burgers-like PDE on nonuniform 2048x4096 grid.
// Inputs (metadata order): t[1], state[2*NX*NY], x[NX], y[NY], mu[1]
// Output: [2, NX, NY] float32.
//
// R10: single kernel. Stencil coefficients computed inline (fast rcp),
// RT=2 with a front-batched 4-row float4 window, launch_bounds(128,5).

#define FULLMASK 0xffffffffu

__device__ __forceinline__ float4 ld4(const float* p) {
    return *reinterpret_cast<const float4*>(p);
}
__device__ __forceinline__ void st4(float* p, float4 v) {
    *reinterpret_cast<float4*>(p) = v;
}
__device__ __forceinline__ float fdiv(float a, float b) {
    return __fdividef(a, b);
}

// Warp owns 128 aligned columns; lane owns 4 (float4). Each thread computes
// 2 consecutive i-rows from a front-batched 4-row window (rows i0-1..i0+2).
// i==0 output rows are fully zeroed by the reference, so garbage x-coeffs
// there (h1=0 -> inf) are dead. i==nx-1 uses the one-sided triple
// rows (nx-3,nx-2,nx-1) = window rows 0..2.
__global__ __launch_bounds__(128, 5)
void rhs_kernel(const float* __restrict__ state,
                const float* __restrict__ xg,
                const float* __restrict__ yg,
                const float* __restrict__ mu_p,
                float* __restrict__ out, int nx, int ny) {
    const int lane = threadIdx.x;
    const int base = blockIdx.x * 128;
    const int j0 = base + lane * 4;
    if (j0 >= ny) return;
    const int i0 = (blockIdx.y * blockDim.y + threadIdx.y) * 2;
    const unsigned plane = (unsigned)nx * (unsigned)ny;
    const float* __restrict__ u = state;
    const float* __restrict__ v = state + plane;

    // ---- front-batched window loads: rows i0-1 .. i0+2 (i-clamped) ----
    float4 uw[4], vw[4];
    {
        unsigned o0 = (unsigned)max(i0 - 1, 0) * (unsigned)ny + (unsigned)j0;
        unsigned o1 = (unsigned)i0 * (unsigned)ny + (unsigned)j0;
        unsigned o2 = (unsigned)(i0 + 1) * (unsigned)ny + (unsigned)j0;
        unsigned o3 = (unsigned)min(i0 + 2, nx - 1) * (unsigned)ny + (unsigned)j0;
        uw[0] = ld4(u + o0); uw[1] = ld4(u + o1);
        uw[2] = ld4(u + o2); uw[3] = ld4(u + o3);
        vw[0] = ld4(v + o0); vw[1] = ld4(v + o1);
        vw[2] = ld4(v + o2); vw[3] = ld4(v + o3);
    }

    // Halo columns (warp-edge neighbors), 2 compute rows.
    float hu[2] = {0.f, 0.f}, hv[2] = {0.f, 0.f};
    const bool is_halo = (lane == 0) || (lane == 31);
    const int jh = (lane == 0) ? max(base - 1, 0) : min(base + 128, ny - 1);
    if (is_halo) {
        unsigned h0 = (unsigned)i0 * (unsigned)ny + (unsigned)jh;
        unsigned h1 = (unsigned)(i0 + 1) * (unsigned)ny + (unsigned)jh;
        hu[0] = __ldg(u + h0); hu[1] = __ldg(u + h1);
        hv[0] = __ldg(v + h0); hv[1] = __ldg(v + h1);
    }

    // x grid values (warp-uniform) for rows i0, i0+1 (+ one-sided support)
    const float xm1 = __ldg(xg + max(i0 - 1, 0));
    const float xc0 = __ldg(xg + i0);
    const float xc1 = __ldg(xg + i0 + 1);
    const float xp  = __ldg(xg + min(i0 + 2, nx - 1));
    const float mu  = mu_p[0];

    // ---- inline y coefficients for this lane's 4 columns ----
    const float ymv = __ldg(yg + max(j0 - 1, 0));
    const float4 ycv = ld4(yg + j0);
    const float ypv = __ldg(yg + min(j0 + 4, ny - 1));
    float G[6] = {ymv, ycv.x, ycv.y, ycv.z, ycv.w, ypv};
    float C0[4], C1[4], C2[4], C3[4], C4[4], C5[4];
#pragma unroll
    for (int e = 0; e < 4; e++) {
        const int jj = j0 + e;
        if (jj == 0) {
            float hA = G[2] - G[1], hB = G[3] - G[2], s = hA + hB;
            float rA = fdiv(1.f, hA * s), rAB = fdiv(1.f, hA * hB), rB = fdiv(1.f, hB * s);
            C0[e] = -(2.f * hA + hB) * rA; C1[e] = s * rAB; C2[e] = -hA * rB;
            C3[e] = 2.f * rA; C4[e] = -2.f * rAB; C5[e] = 2.f * rB;
        } else if (jj == ny - 1) {
            const int em = (e > 0) ? e - 1 : 0;   // dead for e==0
            float hC = G[e] - G[em], hD = G[e + 1] - G[e], s = hC + hD;
            float rC = fdiv(1.f, hC * s), rCD = fdiv(1.f, hC * hD), rD = fdiv(1.f, hD * s);
            C0[e] = hD * rC; C1[e] = -s * rCD; C2[e] = (hC + 2.f * hD) * rD;
            C3[e] = 2.f * rC; C4[e] = -2.f * rCD; C5[e] = 2.f * rD;
        } else {
            float h1 = G[e + 1] - G[e], h2 = G[e + 2] - G[e + 1], s = h1 + h2;
            float r1 = fdiv(1.f, h1 * s), r12 = fdiv(1.f, h1 * h2), r2 = fdiv(1.f, h2 * s);
            C0[e] = -h2 * r1; C1[e] = (h2 - h1) * r12; C2[e] = h1 * r2;
            C3[e] = 2.f * r1; C4[e] = -2.f * r12; C5[e] = 2.f * r2;
        }
    }
    const float4 c1a = make_float4(C0[0], C0[1], C0[2], C0[3]);
    const float4 c1b = make_float4(C1[0], C1[1], C1[2], C1[3]);
    const float4 c1c = make_float4(C2[0], C2[1], C2[2], C2[3]);
    const float4 c2a = make_float4(C3[0], C3[1], C3[2], C3[3]);
    const float4 c2b = make_float4(C4[0], C4[1], C4[2], C4[3]);
    const float4 c2c = make_float4(C5[0], C5[1], C5[2], C5[3]);

    const bool e0b = (j0 == 0);            // column .x is the global left edge
    const bool e3b = (j0 + 3 == ny - 1);   // column .w is the global right edge
    const unsigned obase = (unsigned)i0 * (unsigned)ny + (unsigned)j0;

#pragma unroll
    for (int r = 0; r < 2; r++) {
        const int i = i0 + r;
        const float4 U = uw[r + 1], V = vw[r + 1];

        // Warp-edge neighbors via shuffle; lanes 0/31 patch from halo loads.
        float lu = __shfl_up_sync(FULLMASK, U.w, 1);
        float ru = __shfl_down_sync(FULLMASK, U.x, 1);
        float lv = __shfl_up_sync(FULLMASK, V.w, 1);
        float rv = __shfl_down_sync(FULLMASK, V.x, 1);
        if (lane == 0)  { lu = hu[r]; lv = hv[r]; }
        if (lane == 31) { ru = hu[r]; rv = hv[r]; }

        // Per-element y-stencil triples. At j==0 the one-sided stencil reads
        // columns {0,1,2} = (.x,.y,.z); at j==ny-1 it reads (.y,.z,.w).
        float a0u = e0b ? U.x : lu,  b0u = e0b ? U.y : U.x, g0u = e0b ? U.z : U.y;
        float a0v = e0b ? V.x : lv,  b0v = e0b ? V.y : V.x, g0v = e0b ? V.z : V.y;
        float a3u = e3b ? U.y : U.z, b3u = e3b ? U.z : U.w, g3u = e3b ? U.w : ru;
        float a3v = e3b ? V.y : V.z, b3v = e3b ? V.z : V.w, g3v = e3b ? V.w : rv;

        float4 d1y_u, d2y_u, d1y_v, d2y_v;
        d1y_u.x = c1a.x * a0u + c1b.x * b0u + c1c.x * g0u;
        d2y_u.x = c2a.x * a0u + c2b.x * b0u + c2c.x * g0u;
        d1y_v.x = c1a.x * a0v + c1b.x * b0v + c1c.x * g0v;
        d2y_v.x = c2a.x * a0v + c2b.x * b0v + c2c.x * g0v;

        d1y_u.y = c1a.y * U.x + c1b.y * U.y + c1c.y * U.z;
        d2y_u.y = c2a.y * U.x + c2b.y * U.y + c2c.y * U.z;
        d1y_v.y = c1a.y * V.x + c1b.y * V.y + c1c.y * V.z;
        d2y_v.y = c2a.y * V.x + c2b.y * V.y + c2c.y * V.z;

        d1y_u.z = c1a.z * U.y + c1b.z * U.z + c1c.z * U.w;
        d2y_u.z = c2a.z * U.y + c2b.z * U.z + c2c.z * U.w;
        d1y_v.z = c1a.z * V.y + c1b.z * V.z + c1c.z * V.w;
        d2y_v.z = c2a.z * V.y + c2b.z * V.z + c2c.z * V.w;

        d1y_u.w = c1a.w * a3u + c1b.w * b3u + c1c.w * g3u;
        d2y_u.w = c2a.w * a3u + c2b.w * b3u + c2c.w * g3u;
        d1y_v.w = c1a.w * a3v + c1b.w * b3v + c1c.w * g3v;
        d2y_v.w = c2a.w * a3v + c2b.w * b3v + c2c.w * g3v;

        // ---- inline x coefficients for this row (warp-uniform) ----
        float cx1a, cx1b, cx1c, cx2a, cx2b, cx2c;
        {
            const bool last = (i == nx - 1);       // implies r==1
            float xl = (r == 0) ? xm1 : xc0;       // x[i-1]
            float xm = (r == 0) ? xc0 : xc1;       // x[i]
            float xr = (r == 0) ? xc1 : xp;        // x[i+1]
            if (last) {
                float hC = xc0 - xm1, hD = xc1 - xc0, s = hC + hD;
                float rC = fdiv(1.f, hC * s), rCD = fdiv(1.f, hC * hD), rD = fdiv(1.f, hD * s);
                cx1a = hD * rC; cx1b = -s * rCD; cx1c = (hC + 2.f * hD) * rD;
                cx2a = 2.f * rC; cx2b = -2.f * rCD; cx2c = 2.f * rD;
            } else {
                // i==0 gives h1=0 -> inf coeffs; that row's output is zeroed below.
                float h1 = xm - xl, h2 = xr - xm, s = h1 + h2;
                float r1 = fdiv(1.f, h1 * s), r12 = fdiv(1.f, h1 * h2), r2 = fdiv(1.f, h2 * s);
                cx1a = -h2 * r1; cx1b = (h2 - h1) * r12; cx1c = h1 * r2;
                cx2a = 2.f * r1; cx2b = -2.f * r12; cx2c = 2.f * r2;
            }
        }

        // x-stencil triples: interior rows r,r+1,r+2; one-sided at i==nx-1
        // uses window rows 0..2 (= rows nx-3,nx-2,nx-1).
        const bool last = (i == nx - 1);
        const int b0 = last ? 0 : r;
        const float4 X0 = uw[b0], X1 = uw[b0 + 1], X2 = uw[b0 + 2];
        const float4 Y0 = vw[b0], Y1 = vw[b0 + 1], Y2 = vw[b0 + 2];

        float4 du, dv;
        {
            float d1x, d2x, d1xv, d2xv;
#define DO_ELEM(E) \
            d1x  = cx1a * X0.E + cx1b * X1.E + cx1c * X2.E;              \
            d2x  = cx2a * X0.E + cx2b * X1.E + cx2c * X2.E;              \
            d1xv = cx1a * Y0.E + cx1b * Y1.E + cx1c * Y2.E;              \
            d2xv = cx2a * Y0.E + cx2b * Y1.E + cx2c * Y2.E;              \
            du.E = mu * (d2y_u.E + d2x) - U.E * d1x - V.E * d1y_u.E + 0.01f; \
            dv.E = mu * (d2y_v.E + d2xv) - U.E * d1xv - V.E * d1y_v.E;
            DO_ELEM(x) DO_ELEM(y) DO_ELEM(z) DO_ELEM(w)
#undef DO_ELEM
        }

        // Boundary zeroing per reference (entire i==0 row zeroed for both)
        if (i == 0) { du = make_float4(0.f, 0.f, 0.f, 0.f);
                      dv = make_float4(0.f, 0.f, 0.f, 0.f); }
        if (e0b) { du.x = 0.f; dv.x = 0.f; }
        if (e3b) { du.w = 0.f; }

        unsigned o = obase + (unsigned)r * (unsigned)ny;
        st4(out + o, du);
        st4(out + plane + o, dv);
    }
}

extern "C" void kernel_launch(void* const* d_in, const int* in_sizes, int n_in,
                              void* d_out, int out_size) {
    const float* state = (const float*)d_in[1];
    const float* x = (const float*)d_in[2];
    const float* y = (const float*)d_in[3];
    const float* mu = (const float*)d_in[4];
    int nx = in_sizes[2];
    int ny = in_sizes[3];
    float* out = (float*)d_out;

    dim3 block(32, 4);                        // warp = 128 columns, 8 i-rows/block
    dim3 grid((ny + 127) / 128, (nx + 7) / 8);
    rhs_kernel<<<grid, block>>>(state, x, y, mu, out, nx, ny);
}